// round 12
// baseline (speedup 1.0000x reference)
#include <cuda_runtime.h>
#include <cuda_fp16.h>

#define N_NODES_MAX 100000
#define E_MAX 3200000
#define D 128
#define SPAD 136         // padded smem row stride in halves

// Scratch (allocation-free requirement -> __device__ globals)
__device__ __align__(16) float g_isd[N_NODES_MAX];
__device__ __align__(16) __half g_h16[(size_t)N_NODES_MAX * D];   // gemm1 out
__device__ __align__(16) __half g_h16b[(size_t)N_NODES_MAX * D];  // gemm2 out
__device__ __align__(16) __half g_z16[(size_t)N_NODES_MAX * D];   // gather out
__device__ int g_count[N_NODES_MAX];
__device__ __align__(16) int2 g_rowptr2[N_NODES_MAX];  // (start, end) per node
__device__ int g_cursor[N_NODES_MAX];
__device__ int g_total;                                 // atomic base for scan
__device__ __align__(16) int2 g_edges[E_MAX];          // (src, isd[src] bits)
__device__ int g_is64;
__device__ __align__(16) __half g_W1t[128 * 128];  // W1^T fp16 [n][k]
__device__ __align__(16) __half g_W2t[128 * 128];  // W2^T fp16 [n][k]
__device__ __align__(16) __half g_Wlt[64 * 128];   // Wl^T fp16, n padded 40->64

// ---------------------------------------------------------------------------
// init: zero histogram + scan base, detect edge dtype
// (int64 vs int32: node ids < 2^31 so int64 has all-zero odd 32-bit words)
// ---------------------------------------------------------------------------
__global__ void init_kernel(const unsigned int* __restrict__ w, int* count, int n) {
    int i = blockIdx.x * blockDim.x + threadIdx.x;
    if (i < n) count[i] = 0;
    if (i == 0) g_total = 0;
    if (blockIdx.x == 0) {
        __shared__ int any_nz;
        if (threadIdx.x == 0) any_nz = 0;
        __syncthreads();
        for (int j = threadIdx.x; j < 1024; j += blockDim.x)
            if (w[2 * j + 1] != 0u) any_nz = 1;
        __syncthreads();
        if (threadIdx.x == 0) g_is64 = any_nz ? 0 : 1;
    }
}

__device__ __forceinline__ int edge_at(const unsigned int* __restrict__ w,
                                       size_t pos, int is64) {
    return (int)(is64 ? w[2 * pos] : w[pos]);
}

// ---------------------------------------------------------------------------
// Histogram: 4 edges per thread; uint4 vectorized on the int32 path.
// ---------------------------------------------------------------------------
__global__ void hist_kernel(const unsigned int* __restrict__ ei, int* count, int E) {
    int base = (blockIdx.x * blockDim.x + threadIdx.x) * 4;
    if (base >= E) return;
    int is64 = g_is64;
    if (!is64 && base + 4 <= E) {
        uint4 d = *(const uint4*)(ei + (size_t)E + base);
        atomicAdd(count + (int)d.x, 1);
        atomicAdd(count + (int)d.y, 1);
        atomicAdd(count + (int)d.z, 1);
        atomicAdd(count + (int)d.w, 1);
    } else {
        for (int j = 0; j < 4 && base + j < E; j++)
            atomicAdd(count + edge_at(ei, (size_t)E + base + j, is64), 1);
    }
}

// ---------------------------------------------------------------------------
// Weight prep (one launch): W1t/W2t [128][128], Wlt [64][128] (n>=40 zero)
// ---------------------------------------------------------------------------
__global__ void wt_prep_kernel(const float* __restrict__ W1,
                               const float* __restrict__ W2,
                               const float* __restrict__ Wl,
                               __half* __restrict__ W1t, __half* __restrict__ W2t,
                               __half* __restrict__ Wlt) {
    int idx = blockIdx.x * blockDim.x + threadIdx.x;  // 40960 total
    if (idx < 32768) {
        int which = idx >> 14;
        int r = idx & 16383;
        int n = r >> 7, k = r & 127;
        const float* W = which ? W2 : W1;
        __half* Wt = which ? W2t : W1t;
        Wt[r] = __float2half_rn(W[k * 128 + n]);
    } else if (idx < 40960) {
        int r = idx - 32768;          // 0..8191
        int n = r >> 7, k = r & 127;  // n 0..63
        float v = (n < 40) ? Wl[k * 40 + n] : 0.f;
        Wlt[r] = __float2half_rn(v);
    }
}

// ---------------------------------------------------------------------------
// Order-independent single-pass "scan": each block claims its base via one
// atomicAdd on g_total; rows get disjoint [start,end) spans covering [0,E).
// Also emits isd = rsqrt(deg+1).
// ---------------------------------------------------------------------------
__global__ void scan_kernel(const int* __restrict__ count, int2* rowptr2,
                            int* cursor, float* isd, int n) {
    __shared__ int sm[256];
    __shared__ int s_base;
    const int t = threadIdx.x;
    const int base = blockIdx.x * 1024 + t * 4;

    int v[4];
#pragma unroll
    for (int j = 0; j < 4; j++) {
        int i = base + j;
        v[j] = (i < n) ? count[i] : 0;
        if (i < n) isd[i] = rsqrtf((float)v[j] + 1.0f);  // +1 self loop
    }
    int s = v[0] + v[1] + v[2] + v[3];
    sm[t] = s;
    __syncthreads();
    for (int off = 1; off < 256; off <<= 1) {
        int x = (t >= off) ? sm[t - off] : 0;
        __syncthreads();
        sm[t] += x;
        __syncthreads();
    }
    int local_excl = sm[t] - s;
    if (t == 255) s_base = atomicAdd(&g_total, sm[255]);
    __syncthreads();

    int start = s_base + local_excl;
#pragma unroll
    for (int j = 0; j < 4; j++) {
        int i = base + j;
        if (i < n) {
            rowptr2[i] = make_int2(start, start + v[j]);
            cursor[i] = start;
        }
        start += v[j];
    }
}

// ---------------------------------------------------------------------------
// Scatter: edges[pos] = (src, isd[src]). The dst factor of the norm is
// applied in the gather (register-resident there) — saves the random
// isd[dst] read here.
// ---------------------------------------------------------------------------
__global__ void scatter_kernel(const unsigned int* __restrict__ ei,
                               const float* __restrict__ isd,
                               int* cursor, int2* edges, int E) {
    int base = (blockIdx.x * blockDim.x + threadIdx.x) * 4;
    if (base >= E) return;
    int is64 = g_is64;
    if (!is64 && base + 4 <= E) {
        uint4 s4 = *(const uint4*)(ei + base);
        uint4 d4 = *(const uint4*)(ei + (size_t)E + base);
        int ss[4] = {(int)s4.x, (int)s4.y, (int)s4.z, (int)s4.w};
        int dd[4] = {(int)d4.x, (int)d4.y, (int)d4.z, (int)d4.w};
#pragma unroll
        for (int j = 0; j < 4; j++) {
            int pos = atomicAdd(cursor + dd[j], 1);
            edges[pos] = make_int2(ss[j], __float_as_int(isd[ss[j]]));
        }
    } else {
        for (int j = 0; j < 4 && base + j < E; j++) {
            int s = edge_at(ei, (size_t)(base + j), is64);
            int d = edge_at(ei, (size_t)E + base + j, is64);
            int pos = atomicAdd(cursor + d, 1);
            edges[pos] = make_int2(s, __float_as_int(isd[s]));
        }
    }
}

// ---------------------------------------------------------------------------
// Tensor-core GEMM: h16[M,128] = A[M,128] @ W (fp16 in, fp32 accum, fp16 out)
// IN_HALF=false: A fp32 (layer-1 x). IN_HALF=true: A fp16 (z16, pre-activated).
// ---------------------------------------------------------------------------
__device__ __forceinline__ void mma16816(float c[4], unsigned a0, unsigned a1,
                                         unsigned a2, unsigned a3,
                                         unsigned b0, unsigned b1) {
    asm volatile(
        "mma.sync.aligned.m16n8k16.row.col.f32.f16.f16.f32 "
        "{%0,%1,%2,%3}, {%4,%5,%6,%7}, {%8,%9}, {%0,%1,%2,%3};"
        : "+f"(c[0]), "+f"(c[1]), "+f"(c[2]), "+f"(c[3])
        : "r"(a0), "r"(a1), "r"(a2), "r"(a3), "r"(b0), "r"(b1));
}

template <bool IN_HALF>
__global__ void gemm_tc_kernel(const void* __restrict__ Ain,
                               const __half* __restrict__ Wt16,  // [n][k]
                               __half* __restrict__ Hout,
                               int M) {
    extern __shared__ __half smh[];
    __half* As = smh;              // 64 x SPAD
    __half* Bs = smh + 64 * SPAD;  // 128 x SPAD

    const int tid = threadIdx.x;
    const int r0 = blockIdx.x * 64;

    {
        const uint4* src = (const uint4*)Wt16;
#pragma unroll
        for (int i = 0; i < 8; i++) {
            int idx = tid + i * 256;          // 2048 uint4
            int row = idx >> 4, c8 = idx & 15;
            *(uint4*)(Bs + row * SPAD + c8 * 8) = src[idx];
        }
    }
    if (IN_HALF) {
        const uint4* src = (const uint4*)Ain;
#pragma unroll
        for (int i = 0; i < 4; i++) {
            int idx = tid + i * 256;           // 1024 uint4
            int lr = idx >> 4, c8 = idx & 15;
            int row = r0 + lr;
            uint4 v = make_uint4(0u, 0u, 0u, 0u);
            if (row < M) v = src[(size_t)row * 16 + c8];
            *(uint4*)(As + lr * SPAD + c8 * 8) = v;
        }
    } else {
        const float4* src = (const float4*)Ain;
#pragma unroll
        for (int i = 0; i < 8; i++) {
            int idx = tid + i * 256;           // 2048 float4
            int lr = idx >> 5, c4 = idx & 31;
            int row = r0 + lr;
            float4 v = make_float4(0.f, 0.f, 0.f, 0.f);
            if (row < M) v = src[(size_t)row * 32 + c4];
            __half2 lo = __floats2half2_rn(v.x, v.y);
            __half2 hi = __floats2half2_rn(v.z, v.w);
            uint2 pack;
            pack.x = *(unsigned*)&lo;
            pack.y = *(unsigned*)&hi;
            *(uint2*)(As + lr * SPAD + c4 * 4) = pack;
        }
    }
    __syncthreads();

    const int warp = tid >> 5;
    const int lane = tid & 31;
    const int g = lane >> 2;
    const int tig = lane & 3;
    const int m0 = (warp & 3) * 16;
    const int n0 = (warp >> 2) * 64;

    float c[8][4] = {};
    const __half* Aw = As + (m0 + g) * SPAD + tig * 2;
    const __half* Bw = Bs + (n0 + g) * SPAD + tig * 2;

#pragma unroll
    for (int ks = 0; ks < 8; ks++) {
        int k0 = ks * 16;
        unsigned a0 = *(const unsigned*)(Aw + k0);
        unsigned a1 = *(const unsigned*)(Aw + k0 + 8 * SPAD);
        unsigned a2 = *(const unsigned*)(Aw + k0 + 8);
        unsigned a3 = *(const unsigned*)(Aw + k0 + 8 * SPAD + 8);
#pragma unroll
        for (int t = 0; t < 8; t++) {
            unsigned b0 = *(const unsigned*)(Bw + t * 8 * SPAD + k0);
            unsigned b1 = *(const unsigned*)(Bw + t * 8 * SPAD + k0 + 8);
            mma16816(c[t], a0, a1, a2, a3, b0, b1);
        }
    }

#pragma unroll
    for (int t = 0; t < 8; t++) {
        int col = n0 + t * 8 + tig * 2;
        int row0 = r0 + m0 + g;
        int row1 = row0 + 8;
        if (row0 < M) {
            __half2 p = __floats2half2_rn(c[t][0], c[t][1]);
            *(unsigned*)(Hout + (size_t)row0 * 128 + col) = *(unsigned*)&p;
        }
        if (row1 < M) {
            __half2 p = __floats2half2_rn(c[t][2], c[t][3]);
            *(unsigned*)(Hout + (size_t)row1 * 128 + col) = *(unsigned*)&p;
        }
    }
}

// ---------------------------------------------------------------------------
// CSR gather + fused epilogue over node range [node_base, node_end):
// z16[n] = (half)relu(agg[n] + bias);
// agg[n] = h[n]/deg(n) + sum_e h[src_e] * (isd_src_e * isd[n])
// One warp per node; lane owns 4 columns.
// ---------------------------------------------------------------------------
__device__ __forceinline__ void fma4_h(float4& acc, uint2 p, float w) {
    float2 lo = __half22float2(*(__half2*)&p.x);
    float2 hi = __half22float2(*(__half2*)&p.y);
    acc.x += lo.x * w; acc.y += lo.y * w;
    acc.z += hi.x * w; acc.w += hi.y * w;
}

__global__ void gather_kernel(const int2* __restrict__ edges,
                              const int2* __restrict__ rowptr2,
                              const __half* __restrict__ h,
                              const float* __restrict__ isd,
                              const float* __restrict__ bias,
                              __half* __restrict__ z,
                              int node_base, int node_end) {
    int node = node_base + ((blockIdx.x * blockDim.x + threadIdx.x) >> 5);
    int lane = threadIdx.x & 31;
    if (node >= node_end) return;

    const uint2* h4 = (const uint2*)h;
    int2 span = rowptr2[node];
    int start = span.x;
    int end = span.y;

    float isd_d = isd[node];
    float4 acc = make_float4(0.f, 0.f, 0.f, 0.f);
    fma4_h(acc, h4[(size_t)node * 32 + lane], isd_d * isd_d);  // self loop 1/deg

    int e = start;
    for (; e + 4 <= end; e += 4) {
        int2 e0 = edges[e + 0];
        int2 e1 = edges[e + 1];
        int2 e2 = edges[e + 2];
        int2 e3 = edges[e + 3];
        uint2 v0 = h4[(size_t)e0.x * 32 + lane];
        uint2 v1 = h4[(size_t)e1.x * 32 + lane];
        uint2 v2 = h4[(size_t)e2.x * 32 + lane];
        uint2 v3 = h4[(size_t)e3.x * 32 + lane];
        fma4_h(acc, v0, __int_as_float(e0.y) * isd_d);
        fma4_h(acc, v1, __int_as_float(e1.y) * isd_d);
        fma4_h(acc, v2, __int_as_float(e2.y) * isd_d);
        fma4_h(acc, v3, __int_as_float(e3.y) * isd_d);
    }
    for (; e < end; e++) {
        int2 ed = edges[e];
        fma4_h(acc, h4[(size_t)ed.x * 32 + lane], __int_as_float(ed.y) * isd_d);
    }

    float4 b = ((const float4*)bias)[lane];
    acc.x = fmaxf(acc.x + b.x, 0.f);
    acc.y = fmaxf(acc.y + b.y, 0.f);
    acc.z = fmaxf(acc.z + b.z, 0.f);
    acc.w = fmaxf(acc.w + b.w, 0.f);
    __half2 lo = __floats2half2_rn(acc.x, acc.y);
    __half2 hi = __floats2half2_rn(acc.z, acc.w);
    uint2 p;
    p.x = *(unsigned*)&lo;
    p.y = *(unsigned*)&hi;
    ((uint2*)z)[(size_t)node * 32 + lane] = p;
}

// ---------------------------------------------------------------------------
// Tensor-core head: out[M,40] = z16[M,128] @ Wl + bl (Wlt [64][128] fp16)
// ---------------------------------------------------------------------------
__global__ void head_tc_kernel(const __half* __restrict__ z,
                               const __half* __restrict__ Wlt,  // [64][128]
                               const float* __restrict__ bl,
                               float* __restrict__ out,
                               int M) {
    extern __shared__ __half smh[];
    __half* As = smh;              // 64 x SPAD
    __half* Bs = smh + 64 * SPAD;  // 64 x SPAD

    const int tid = threadIdx.x;   // 256
    const int r0 = blockIdx.x * 64;

    {
        const uint4* src = (const uint4*)Wlt;   // 1024 uint4
#pragma unroll
        for (int i = 0; i < 4; i++) {
            int idx = tid + i * 256;
            int row = idx >> 4, c8 = idx & 15;
            *(uint4*)(Bs + row * SPAD + c8 * 8) = src[idx];
        }
    }
    {
        const uint4* src = (const uint4*)z;
#pragma unroll
        for (int i = 0; i < 4; i++) {
            int idx = tid + i * 256;           // 1024 uint4
            int lr = idx >> 4, c8 = idx & 15;
            int row = r0 + lr;
            uint4 v = make_uint4(0u, 0u, 0u, 0u);
            if (row < M) v = src[(size_t)row * 16 + c8];
            *(uint4*)(As + lr * SPAD + c8 * 8) = v;
        }
    }
    __syncthreads();

    const int warp = tid >> 5;
    const int lane = tid & 31;
    const int g = lane >> 2;
    const int tig = lane & 3;
    const int m0 = (warp & 3) * 16;
    const int n0 = (warp >> 2) * 32;

    float c[4][4] = {};
    const __half* Aw = As + (m0 + g) * SPAD + tig * 2;
    const __half* Bw = Bs + (n0 + g) * SPAD + tig * 2;

#pragma unroll
    for (int ks = 0; ks < 8; ks++) {
        int k0 = ks * 16;
        unsigned a0 = *(const unsigned*)(Aw + k0);
        unsigned a1 = *(const unsigned*)(Aw + k0 + 8 * SPAD);
        unsigned a2 = *(const unsigned*)(Aw + k0 + 8);
        unsigned a3 = *(const unsigned*)(Aw + k0 + 8 * SPAD + 8);
#pragma unroll
        for (int t = 0; t < 4; t++) {
            unsigned b0 = *(const unsigned*)(Bw + t * 8 * SPAD + k0);
            unsigned b1 = *(const unsigned*)(Bw + t * 8 * SPAD + k0 + 8);
            mma16816(c[t], a0, a1, a2, a3, b0, b1);
        }
    }

#pragma unroll
    for (int t = 0; t < 4; t++) {
        int col = n0 + t * 8 + tig * 2;
        if (col < 40) {
            float b0 = bl[col], b1 = bl[col + 1];
            int row0 = r0 + m0 + g;
            int row1 = row0 + 8;
            if (row0 < M) {
                float2 p = make_float2(c[t][0] + b0, c[t][1] + b1);
                *(float2*)(out + (size_t)row0 * 40 + col) = p;
            }
            if (row1 < M) {
                float2 p = make_float2(c[t][2] + b0, c[t][3] + b1);
                *(float2*)(out + (size_t)row1 * 40 + col) = p;
            }
        }
    }
}

// ---------------------------------------------------------------------------
extern "C" void kernel_launch(void* const* d_in, const int* in_sizes, int n_in,
                              void* d_out, int out_size) {
    const float* x = (const float*)d_in[0];
    const unsigned int* ei = (const unsigned int*)d_in[1];
    const float* W1 = (const float*)d_in[2];
    const float* b1 = (const float*)d_in[3];
    const float* W2 = (const float*)d_in[4];
    const float* b2 = (const float*)d_in[5];
    const float* Wl = (const float*)d_in[6];
    const float* bl = (const float*)d_in[7];
    float* out = (float*)d_out;

    const int N = in_sizes[0] / D;     // 100000
    const int E = in_sizes[1] / 2;     // 3200000
    const int N2 = N / 2;              // 50000 (even split)

    float* isd;
    __half *h16, *h16b, *z16, *W1t, *W2t, *Wlt;
    int *count, *cursor;
    int2 *rowptr2, *edges;
    cudaGetSymbolAddress((void**)&isd, g_isd);
    cudaGetSymbolAddress((void**)&h16, g_h16);
    cudaGetSymbolAddress((void**)&h16b, g_h16b);
    cudaGetSymbolAddress((void**)&z16, g_z16);
    cudaGetSymbolAddress((void**)&count, g_count);
    cudaGetSymbolAddress((void**)&rowptr2, g_rowptr2);
    cudaGetSymbolAddress((void**)&cursor, g_cursor);
    cudaGetSymbolAddress((void**)&edges, g_edges);
    cudaGetSymbolAddress((void**)&W1t, g_W1t);
    cudaGetSymbolAddress((void**)&W2t, g_W2t);
    cudaGetSymbolAddress((void**)&Wlt, g_Wlt);

    const int gemm_smem = (64 * SPAD + 128 * SPAD) * sizeof(__half);  // ~52 KB
    const int head_smem = (64 * SPAD + 64 * SPAD) * sizeof(__half);   // ~35 KB
    cudaFuncSetAttribute(gemm_tc_kernel<false>,
                         cudaFuncAttributeMaxDynamicSharedMemorySize, gemm_smem);
    cudaFuncSetAttribute(gemm_tc_kernel<true>,
                         cudaFuncAttributeMaxDynamicSharedMemorySize, gemm_smem);
    cudaFuncSetAttribute(head_tc_kernel,
                         cudaFuncAttributeMaxDynamicSharedMemorySize, head_smem);

    // Lazy one-time host-side resources (validated pattern from round 11).
    static cudaStream_t s2 = nullptr;
    static cudaEvent_t ev0 = nullptr, ev1 = nullptr, ev2 = nullptr,
                       ev3 = nullptr, ev4 = nullptr, ev5 = nullptr;
    if (s2 == nullptr) {
        cudaStreamCreateWithFlags(&s2, cudaStreamNonBlocking);
        cudaEventCreateWithFlags(&ev0, cudaEventDisableTiming);
        cudaEventCreateWithFlags(&ev1, cudaEventDisableTiming);
        cudaEventCreateWithFlags(&ev2, cudaEventDisableTiming);
        cudaEventCreateWithFlags(&ev3, cudaEventDisableTiming);
        cudaEventCreateWithFlags(&ev4, cudaEventDisableTiming);
        cudaEventCreateWithFlags(&ev5, cudaEventDisableTiming);
    }

    const int nb = (N + 255) / 256;
    const int e4 = (E + 3) / 4;
    const int eb4 = (e4 + 255) / 256;
    const int scan_grid = (N + 1023) / 1024;
    const int gemm_grid = (N + 63) / 64;
    const int gemm_grid_h = (N2 + 63) / 64;
    const int gather_grid_h = (N2 + 7) / 8;
    const int gather_grid_r = (N - N2 + 7) / 8;
    const int head_grid_h = (N2 + 63) / 64;
    const int head_grid_r = (N - N2 + 63) / 64;

    // 0. init + dtype detect, weight prep (main)
    init_kernel<<<nb, 256>>>(ei, count, N);
    wt_prep_kernel<<<160, 256>>>(W1, W2, Wl, W1t, W2t, Wlt);

    // Fork: gemm1 (x @ W1 -> h16) on s2, concurrent with the CSR build chain.
    cudaEventRecord(ev0, 0);
    cudaStreamWaitEvent(s2, ev0, 0);
    gemm_tc_kernel<false><<<gemm_grid, 256, gemm_smem, s2>>>(x, W1t, h16, N);
    cudaEventRecord(ev1, s2);

    // CSR build on main
    hist_kernel<<<eb4, 256>>>(ei, count, E);
    scan_kernel<<<scan_grid, 256>>>(count, rowptr2, cursor, isd, N);
    scatter_kernel<<<eb4, 256>>>(ei, isd, cursor, edges, E);

    cudaStreamWaitEvent(0, ev1, 0);  // gather1 needs h16 + CSR

    // 1a. gather1_A: z16[0,N2) = relu(agg(h16) + b1)
    gather_kernel<<<gather_grid_h, 256>>>(edges, rowptr2, h16, isd, b1, z16, 0, N2);
    cudaEventRecord(ev2, 0);

    // 2a. gemm2_A on s2 (reads z16[0,N2), writes h16b[0,N2)) — overlaps gather1_B
    cudaStreamWaitEvent(s2, ev2, 0);
    gemm_tc_kernel<true><<<gemm_grid_h, 256, gemm_smem, s2>>>(z16, W2t, h16b, N2);
    cudaEventRecord(ev3, s2);

    // 1b. gather1_B on main (reads h16 all rows, writes z16[N2,N))
    gather_kernel<<<gather_grid_r, 256>>>(edges, rowptr2, h16, isd, b1, z16, N2, N);

    // 2b. gemm2_B on main: h16b[N2,N) = z16[N2,N) @ W2
    gemm_tc_kernel<true><<<gemm_grid_h, 256, gemm_smem>>>(
        z16 + (size_t)N2 * D, W2t, h16b + (size_t)N2 * D, N - N2);

    cudaStreamWaitEvent(0, ev3, 0);  // gather2 needs ALL of h16b

    // 3a. gather2_A: z16[0,N2) = relu(agg(h16b) + b2)
    gather_kernel<<<gather_grid_h, 256>>>(edges, rowptr2, h16b, isd, b2, z16, 0, N2);
    cudaEventRecord(ev4, 0);

    // 4a. head_A on s2 (reads z16[0,N2)) — overlaps gather2_B
    cudaStreamWaitEvent(s2, ev4, 0);
    head_tc_kernel<<<head_grid_h, 256, head_smem, s2>>>(z16, Wlt, bl, out, N2);
    cudaEventRecord(ev5, s2);

    // 3b. gather2_B on main (writes z16[N2,N), disjoint from head_A reads)
    gather_kernel<<<gather_grid_r, 256>>>(edges, rowptr2, h16b, isd, b2, z16, N2, N);

    // 4b. head_B on main
    head_tc_kernel<<<head_grid_r, 256, head_smem>>>(
        z16 + (size_t)N2 * D, Wlt, bl, out + (size_t)N2 * 40, N - N2);

    cudaStreamWaitEvent(0, ev5, 0);  // join all side-stream work before return
}

// round 13
// speedup vs baseline: 1.0457x; 1.0457x over previous
#include <cuda_runtime.h>
#include <cuda_fp16.h>

#define N_NODES_MAX 100000
#define E_MAX 3200000
#define D 128
#define SPAD 136         // padded smem row stride in halves

// Scratch (allocation-free requirement -> __device__ globals)
__device__ __align__(16) float g_isd[N_NODES_MAX];
__device__ __align__(16) __half g_h16[(size_t)N_NODES_MAX * D];  // GEMM out / gather src
__device__ __align__(16) __half g_z16[(size_t)N_NODES_MAX * D];  // gather out relu(agg+b)
__device__ int g_count[N_NODES_MAX];
__device__ __align__(16) int2 g_rowptr2[N_NODES_MAX];  // (start, end) per node
__device__ int g_cursor[N_NODES_MAX];
__device__ int g_total;                                 // atomic base for scan
__device__ __align__(16) int2 g_edges[E_MAX];          // (src, isd[src] bits)
__device__ int g_is64;
__device__ __align__(16) __half g_W1t[128 * 128];  // W1^T fp16 [n][k]
__device__ __align__(16) __half g_W2t[128 * 128];  // W2^T fp16 [n][k]
__device__ __align__(16) __half g_Wlt[64 * 128];   // Wl^T fp16, n padded 40->64

// ---------------------------------------------------------------------------
// init: zero histogram + scan base, detect edge dtype
// (int64 vs int32: node ids < 2^31 so int64 has all-zero odd 32-bit words)
// ---------------------------------------------------------------------------
__global__ void init_kernel(const unsigned int* __restrict__ w, int* count, int n) {
    int i = blockIdx.x * blockDim.x + threadIdx.x;
    if (i < n) count[i] = 0;
    if (i == 0) g_total = 0;
    if (blockIdx.x == 0) {
        __shared__ int any_nz;
        if (threadIdx.x == 0) any_nz = 0;
        __syncthreads();
        for (int j = threadIdx.x; j < 1024; j += blockDim.x)
            if (w[2 * j + 1] != 0u) any_nz = 1;
        __syncthreads();
        if (threadIdx.x == 0) g_is64 = any_nz ? 0 : 1;
    }
}

__device__ __forceinline__ int edge_at(const unsigned int* __restrict__ w,
                                       size_t pos, int is64) {
    return (int)(is64 ? w[2 * pos] : w[pos]);
}

// ---------------------------------------------------------------------------
// Histogram: 4 edges per thread; uint4 vectorized on the int32 path.
// ---------------------------------------------------------------------------
__global__ void hist_kernel(const unsigned int* __restrict__ ei, int* count, int E) {
    int base = (blockIdx.x * blockDim.x + threadIdx.x) * 4;
    if (base >= E) return;
    int is64 = g_is64;
    if (!is64 && base + 4 <= E) {
        uint4 d = *(const uint4*)(ei + (size_t)E + base);
        atomicAdd(count + (int)d.x, 1);
        atomicAdd(count + (int)d.y, 1);
        atomicAdd(count + (int)d.z, 1);
        atomicAdd(count + (int)d.w, 1);
    } else {
        for (int j = 0; j < 4 && base + j < E; j++)
            atomicAdd(count + edge_at(ei, (size_t)E + base + j, is64), 1);
    }
}

// ---------------------------------------------------------------------------
// Weight prep (one launch): W1t/W2t [128][128], Wlt [64][128] (n>=40 zero)
// ---------------------------------------------------------------------------
__global__ void wt_prep_kernel(const float* __restrict__ W1,
                               const float* __restrict__ W2,
                               const float* __restrict__ Wl,
                               __half* __restrict__ W1t, __half* __restrict__ W2t,
                               __half* __restrict__ Wlt) {
    int idx = blockIdx.x * blockDim.x + threadIdx.x;  // 40960 total
    if (idx < 32768) {
        int which = idx >> 14;
        int r = idx & 16383;
        int n = r >> 7, k = r & 127;
        const float* W = which ? W2 : W1;
        __half* Wt = which ? W2t : W1t;
        Wt[r] = __float2half_rn(W[k * 128 + n]);
    } else if (idx < 40960) {
        int r = idx - 32768;          // 0..8191
        int n = r >> 7, k = r & 127;  // n 0..63
        float v = (n < 40) ? Wl[k * 40 + n] : 0.f;
        Wlt[r] = __float2half_rn(v);
    }
}

// ---------------------------------------------------------------------------
// Order-independent single-pass "scan": each block claims its base via one
// atomicAdd on g_total; rows get disjoint [start,end) spans covering [0,E).
// Also emits isd = rsqrt(deg+1).
// ---------------------------------------------------------------------------
__global__ void scan_kernel(const int* __restrict__ count, int2* rowptr2,
                            int* cursor, float* isd, int n) {
    __shared__ int sm[256];
    __shared__ int s_base;
    const int t = threadIdx.x;
    const int base = blockIdx.x * 1024 + t * 4;

    int v[4];
#pragma unroll
    for (int j = 0; j < 4; j++) {
        int i = base + j;
        v[j] = (i < n) ? count[i] : 0;
        if (i < n) isd[i] = rsqrtf((float)v[j] + 1.0f);  // +1 self loop
    }
    int s = v[0] + v[1] + v[2] + v[3];
    sm[t] = s;
    __syncthreads();
    for (int off = 1; off < 256; off <<= 1) {
        int x = (t >= off) ? sm[t - off] : 0;
        __syncthreads();
        sm[t] += x;
        __syncthreads();
    }
    int local_excl = sm[t] - s;
    if (t == 255) s_base = atomicAdd(&g_total, sm[255]);
    __syncthreads();

    int start = s_base + local_excl;
#pragma unroll
    for (int j = 0; j < 4; j++) {
        int i = base + j;
        if (i < n) {
            rowptr2[i] = make_int2(start, start + v[j]);
            cursor[i] = start;
        }
        start += v[j];
    }
}

// ---------------------------------------------------------------------------
// Scatter: edges[pos] = (src, isd[src]). The dst factor of the norm is
// applied in the gather (register-resident there) — saves the random
// isd[dst] read here.
// ---------------------------------------------------------------------------
__global__ void scatter_kernel(const unsigned int* __restrict__ ei,
                               const float* __restrict__ isd,
                               int* cursor, int2* edges, int E) {
    int base = (blockIdx.x * blockDim.x + threadIdx.x) * 4;
    if (base >= E) return;
    int is64 = g_is64;
    if (!is64 && base + 4 <= E) {
        uint4 s4 = *(const uint4*)(ei + base);
        uint4 d4 = *(const uint4*)(ei + (size_t)E + base);
        int ss[4] = {(int)s4.x, (int)s4.y, (int)s4.z, (int)s4.w};
        int dd[4] = {(int)d4.x, (int)d4.y, (int)d4.z, (int)d4.w};
#pragma unroll
        for (int j = 0; j < 4; j++) {
            int pos = atomicAdd(cursor + dd[j], 1);
            edges[pos] = make_int2(ss[j], __float_as_int(isd[ss[j]]));
        }
    } else {
        for (int j = 0; j < 4 && base + j < E; j++) {
            int s = edge_at(ei, (size_t)(base + j), is64);
            int d = edge_at(ei, (size_t)E + base + j, is64);
            int pos = atomicAdd(cursor + d, 1);
            edges[pos] = make_int2(s, __float_as_int(isd[s]));
        }
    }
}

// ---------------------------------------------------------------------------
// Tensor-core GEMM: h16[M,128] = A[M,128] @ W (fp16 in, fp32 accum, fp16 out)
// IN_HALF=false: A fp32 (layer-1 x). IN_HALF=true: A fp16 (z16, pre-activated).
// ---------------------------------------------------------------------------
__device__ __forceinline__ void mma16816(float c[4], unsigned a0, unsigned a1,
                                         unsigned a2, unsigned a3,
                                         unsigned b0, unsigned b1) {
    asm volatile(
        "mma.sync.aligned.m16n8k16.row.col.f32.f16.f16.f32 "
        "{%0,%1,%2,%3}, {%4,%5,%6,%7}, {%8,%9}, {%0,%1,%2,%3};"
        : "+f"(c[0]), "+f"(c[1]), "+f"(c[2]), "+f"(c[3])
        : "r"(a0), "r"(a1), "r"(a2), "r"(a3), "r"(b0), "r"(b1));
}

template <bool IN_HALF>
__global__ void gemm_tc_kernel(const void* __restrict__ Ain,
                               const __half* __restrict__ Wt16,  // [n][k]
                               __half* __restrict__ Hout,
                               int M) {
    extern __shared__ __half smh[];
    __half* As = smh;              // 64 x SPAD
    __half* Bs = smh + 64 * SPAD;  // 128 x SPAD

    const int tid = threadIdx.x;
    const int r0 = blockIdx.x * 64;

    {
        const uint4* src = (const uint4*)Wt16;
#pragma unroll
        for (int i = 0; i < 8; i++) {
            int idx = tid + i * 256;          // 2048 uint4
            int row = idx >> 4, c8 = idx & 15;
            *(uint4*)(Bs + row * SPAD + c8 * 8) = src[idx];
        }
    }
    if (IN_HALF) {
        const uint4* src = (const uint4*)Ain;
#pragma unroll
        for (int i = 0; i < 4; i++) {
            int idx = tid + i * 256;           // 1024 uint4
            int lr = idx >> 4, c8 = idx & 15;
            int row = r0 + lr;
            uint4 v = make_uint4(0u, 0u, 0u, 0u);
            if (row < M) v = src[(size_t)row * 16 + c8];
            *(uint4*)(As + lr * SPAD + c8 * 8) = v;
        }
    } else {
        const float4* src = (const float4*)Ain;
#pragma unroll
        for (int i = 0; i < 8; i++) {
            int idx = tid + i * 256;           // 2048 float4
            int lr = idx >> 5, c4 = idx & 31;
            int row = r0 + lr;
            float4 v = make_float4(0.f, 0.f, 0.f, 0.f);
            if (row < M) v = src[(size_t)row * 32 + c4];
            __half2 lo = __floats2half2_rn(v.x, v.y);
            __half2 hi = __floats2half2_rn(v.z, v.w);
            uint2 pack;
            pack.x = *(unsigned*)&lo;
            pack.y = *(unsigned*)&hi;
            *(uint2*)(As + lr * SPAD + c4 * 4) = pack;
        }
    }
    __syncthreads();

    const int warp = tid >> 5;
    const int lane = tid & 31;
    const int g = lane >> 2;
    const int tig = lane & 3;
    const int m0 = (warp & 3) * 16;
    const int n0 = (warp >> 2) * 64;

    float c[8][4] = {};
    const __half* Aw = As + (m0 + g) * SPAD + tig * 2;
    const __half* Bw = Bs + (n0 + g) * SPAD + tig * 2;

#pragma unroll
    for (int ks = 0; ks < 8; ks++) {
        int k0 = ks * 16;
        unsigned a0 = *(const unsigned*)(Aw + k0);
        unsigned a1 = *(const unsigned*)(Aw + k0 + 8 * SPAD);
        unsigned a2 = *(const unsigned*)(Aw + k0 + 8);
        unsigned a3 = *(const unsigned*)(Aw + k0 + 8 * SPAD + 8);
#pragma unroll
        for (int t = 0; t < 8; t++) {
            unsigned b0 = *(const unsigned*)(Bw + t * 8 * SPAD + k0);
            unsigned b1 = *(const unsigned*)(Bw + t * 8 * SPAD + k0 + 8);
            mma16816(c[t], a0, a1, a2, a3, b0, b1);
        }
    }

#pragma unroll
    for (int t = 0; t < 8; t++) {
        int col = n0 + t * 8 + tig * 2;
        int row0 = r0 + m0 + g;
        int row1 = row0 + 8;
        if (row0 < M) {
            __half2 p = __floats2half2_rn(c[t][0], c[t][1]);
            *(unsigned*)(Hout + (size_t)row0 * 128 + col) = *(unsigned*)&p;
        }
        if (row1 < M) {
            __half2 p = __floats2half2_rn(c[t][2], c[t][3]);
            *(unsigned*)(Hout + (size_t)row1 * 128 + col) = *(unsigned*)&p;
        }
    }
}

// ---------------------------------------------------------------------------
// CSR gather + fused epilogue: z16[n] = (half)relu(agg[n] + bias)
// agg[n] = h[n]/deg(n) + sum_e h[src_e] * (isd_src_e * isd[n])
// One warp per node; lane owns 4 columns.
// ---------------------------------------------------------------------------
__device__ __forceinline__ void fma4_h(float4& acc, uint2 p, float w) {
    float2 lo = __half22float2(*(__half2*)&p.x);
    float2 hi = __half22float2(*(__half2*)&p.y);
    acc.x += lo.x * w; acc.y += lo.y * w;
    acc.z += hi.x * w; acc.w += hi.y * w;
}

__global__ void gather_kernel(const int2* __restrict__ edges,
                              const int2* __restrict__ rowptr2,
                              const __half* __restrict__ h,
                              const float* __restrict__ isd,
                              const float* __restrict__ bias,
                              __half* __restrict__ z, int N) {
    int node = (blockIdx.x * blockDim.x + threadIdx.x) >> 5;
    int lane = threadIdx.x & 31;
    if (node >= N) return;

    const uint2* h4 = (const uint2*)h;
    int2 span = rowptr2[node];
    int start = span.x;
    int end = span.y;

    float isd_d = isd[node];
    float4 acc = make_float4(0.f, 0.f, 0.f, 0.f);
    fma4_h(acc, h4[(size_t)node * 32 + lane], isd_d * isd_d);  // self loop 1/deg

    int e = start;
    for (; e + 4 <= end; e += 4) {
        int2 e0 = edges[e + 0];
        int2 e1 = edges[e + 1];
        int2 e2 = edges[e + 2];
        int2 e3 = edges[e + 3];
        uint2 v0 = h4[(size_t)e0.x * 32 + lane];
        uint2 v1 = h4[(size_t)e1.x * 32 + lane];
        uint2 v2 = h4[(size_t)e2.x * 32 + lane];
        uint2 v3 = h4[(size_t)e3.x * 32 + lane];
        fma4_h(acc, v0, __int_as_float(e0.y) * isd_d);
        fma4_h(acc, v1, __int_as_float(e1.y) * isd_d);
        fma4_h(acc, v2, __int_as_float(e2.y) * isd_d);
        fma4_h(acc, v3, __int_as_float(e3.y) * isd_d);
    }
    for (; e < end; e++) {
        int2 ed = edges[e];
        fma4_h(acc, h4[(size_t)ed.x * 32 + lane], __int_as_float(ed.y) * isd_d);
    }

    float4 b = ((const float4*)bias)[lane];
    acc.x = fmaxf(acc.x + b.x, 0.f);
    acc.y = fmaxf(acc.y + b.y, 0.f);
    acc.z = fmaxf(acc.z + b.z, 0.f);
    acc.w = fmaxf(acc.w + b.w, 0.f);
    __half2 lo = __floats2half2_rn(acc.x, acc.y);
    __half2 hi = __floats2half2_rn(acc.z, acc.w);
    uint2 p;
    p.x = *(unsigned*)&lo;
    p.y = *(unsigned*)&hi;
    ((uint2*)z)[(size_t)node * 32 + lane] = p;
}

// ---------------------------------------------------------------------------
// Tensor-core head: out[M,40] = z16[M,128] @ Wl + bl (Wlt [64][128] fp16)
// ---------------------------------------------------------------------------
__global__ void head_tc_kernel(const __half* __restrict__ z,
                               const __half* __restrict__ Wlt,  // [64][128]
                               const float* __restrict__ bl,
                               float* __restrict__ out,
                               int M) {
    extern __shared__ __half smh[];
    __half* As = smh;              // 64 x SPAD
    __half* Bs = smh + 64 * SPAD;  // 64 x SPAD

    const int tid = threadIdx.x;   // 256
    const int r0 = blockIdx.x * 64;

    {
        const uint4* src = (const uint4*)Wlt;   // 1024 uint4
#pragma unroll
        for (int i = 0; i < 4; i++) {
            int idx = tid + i * 256;
            int row = idx >> 4, c8 = idx & 15;
            *(uint4*)(Bs + row * SPAD + c8 * 8) = src[idx];
        }
    }
    {
        const uint4* src = (const uint4*)z;
#pragma unroll
        for (int i = 0; i < 4; i++) {
            int idx = tid + i * 256;           // 1024 uint4
            int lr = idx >> 4, c8 = idx & 15;
            int row = r0 + lr;
            uint4 v = make_uint4(0u, 0u, 0u, 0u);
            if (row < M) v = src[(size_t)row * 16 + c8];
            *(uint4*)(As + lr * SPAD + c8 * 8) = v;
        }
    }
    __syncthreads();

    const int warp = tid >> 5;
    const int lane = tid & 31;
    const int g = lane >> 2;
    const int tig = lane & 3;
    const int m0 = (warp & 3) * 16;
    const int n0 = (warp >> 2) * 32;

    float c[4][4] = {};
    const __half* Aw = As + (m0 + g) * SPAD + tig * 2;
    const __half* Bw = Bs + (n0 + g) * SPAD + tig * 2;

#pragma unroll
    for (int ks = 0; ks < 8; ks++) {
        int k0 = ks * 16;
        unsigned a0 = *(const unsigned*)(Aw + k0);
        unsigned a1 = *(const unsigned*)(Aw + k0 + 8 * SPAD);
        unsigned a2 = *(const unsigned*)(Aw + k0 + 8);
        unsigned a3 = *(const unsigned*)(Aw + k0 + 8 * SPAD + 8);
#pragma unroll
        for (int t = 0; t < 4; t++) {
            unsigned b0 = *(const unsigned*)(Bw + t * 8 * SPAD + k0);
            unsigned b1 = *(const unsigned*)(Bw + t * 8 * SPAD + k0 + 8);
            mma16816(c[t], a0, a1, a2, a3, b0, b1);
        }
    }

#pragma unroll
    for (int t = 0; t < 4; t++) {
        int col = n0 + t * 8 + tig * 2;
        if (col < 40) {
            float b0 = bl[col], b1 = bl[col + 1];
            int row0 = r0 + m0 + g;
            int row1 = row0 + 8;
            if (row0 < M) {
                float2 p = make_float2(c[t][0] + b0, c[t][1] + b1);
                *(float2*)(out + (size_t)row0 * 40 + col) = p;
            }
            if (row1 < M) {
                float2 p = make_float2(c[t][2] + b0, c[t][3] + b1);
                *(float2*)(out + (size_t)row1 * 40 + col) = p;
            }
        }
    }
}

// ---------------------------------------------------------------------------
extern "C" void kernel_launch(void* const* d_in, const int* in_sizes, int n_in,
                              void* d_out, int out_size) {
    const float* x = (const float*)d_in[0];
    const unsigned int* ei = (const unsigned int*)d_in[1];
    const float* W1 = (const float*)d_in[2];
    const float* b1 = (const float*)d_in[3];
    const float* W2 = (const float*)d_in[4];
    const float* b2 = (const float*)d_in[5];
    const float* Wl = (const float*)d_in[6];
    const float* bl = (const float*)d_in[7];
    float* out = (float*)d_out;

    const int N = in_sizes[0] / D;     // 100000
    const int E = in_sizes[1] / 2;     // 3200000

    float* isd;
    __half *h16, *z16, *W1t, *W2t, *Wlt;
    int *count, *cursor;
    int2 *rowptr2, *edges;
    cudaGetSymbolAddress((void**)&isd, g_isd);
    cudaGetSymbolAddress((void**)&h16, g_h16);
    cudaGetSymbolAddress((void**)&z16, g_z16);
    cudaGetSymbolAddress((void**)&count, g_count);
    cudaGetSymbolAddress((void**)&rowptr2, g_rowptr2);
    cudaGetSymbolAddress((void**)&cursor, g_cursor);
    cudaGetSymbolAddress((void**)&edges, g_edges);
    cudaGetSymbolAddress((void**)&W1t, g_W1t);
    cudaGetSymbolAddress((void**)&W2t, g_W2t);
    cudaGetSymbolAddress((void**)&Wlt, g_Wlt);

    const int gemm_smem = (64 * SPAD + 128 * SPAD) * sizeof(__half);  // ~52 KB
    const int head_smem = (64 * SPAD + 64 * SPAD) * sizeof(__half);   // ~35 KB
    cudaFuncSetAttribute(gemm_tc_kernel<false>,
                         cudaFuncAttributeMaxDynamicSharedMemorySize, gemm_smem);
    cudaFuncSetAttribute(gemm_tc_kernel<true>,
                         cudaFuncAttributeMaxDynamicSharedMemorySize, gemm_smem);
    cudaFuncSetAttribute(head_tc_kernel,
                         cudaFuncAttributeMaxDynamicSharedMemorySize, head_smem);

    // Lazy one-time host-side resources (validated pattern from round 11).
    static cudaStream_t s2 = nullptr;
    static cudaEvent_t ev_fork = nullptr, ev_join = nullptr;
    if (s2 == nullptr) {
        cudaStreamCreateWithFlags(&s2, cudaStreamNonBlocking);
        cudaEventCreateWithFlags(&ev_fork, cudaEventDisableTiming);
        cudaEventCreateWithFlags(&ev_join, cudaEventDisableTiming);
    }

    const int nb = (N + 255) / 256;
    const int e4 = (E + 3) / 4;
    const int eb4 = (e4 + 255) / 256;
    const int scan_grid = (N + 1023) / 1024;
    const int gemm_grid = (N + 63) / 64;
    const int gather_grid = (N + 7) / 8;
    const int head_grid = (N + 63) / 64;

    // 0. init + dtype detect, weight prep
    init_kernel<<<nb, 256>>>(ei, count, N);
    wt_prep_kernel<<<160, 256>>>(W1, W2, Wl, W1t, W2t, Wlt);

    // Fork: gemm1 (x @ W1 -> h16) on s2, concurrent with the CSR build chain
    // (validated in round 11: gemm is tensor/smem-bound, CSR build is
    // atomic-bound — different resources, real overlap).
    cudaEventRecord(ev_fork, 0);
    cudaStreamWaitEvent(s2, ev_fork, 0);
    gemm_tc_kernel<false><<<gemm_grid, 256, gemm_smem, s2>>>(x, W1t, h16, N);
    cudaEventRecord(ev_join, s2);

    // CSR build on main stream
    hist_kernel<<<eb4, 256>>>(ei, count, E);
    scan_kernel<<<scan_grid, 256>>>(count, rowptr2, cursor, isd, N);
    scatter_kernel<<<eb4, 256>>>(ei, isd, cursor, edges, E);

    cudaStreamWaitEvent(0, ev_join, 0);  // gather1 needs h16 + CSR

    // 1. layer 1 aggregate: z16 = relu(agg(h16) + b1)
    gather_kernel<<<gather_grid, 256>>>(edges, rowptr2, h16, isd, b1, z16, N);

    // 2. layer 2: h16 = (half)(z16 @ W2); z16 = relu(agg + b2)
    gemm_tc_kernel<true><<<gemm_grid, 256, gemm_smem>>>(z16, W2t, h16, N);
    gather_kernel<<<gather_grid, 256>>>(edges, rowptr2, h16, isd, b2, z16, N);

    // 3. head: out = z16 @ Wl + bl   (tensor cores)
    head_tc_kernel<<<head_grid, 256, head_smem>>>(z16, Wlt, bl, out, N);
}

// round 14
// speedup vs baseline: 1.0664x; 1.0197x over previous
#include <cuda_runtime.h>
#include <cuda_fp16.h>

#define N_NODES_MAX 100000
#define E_MAX 3200000
#define D 128
#define SPAD 136         // padded smem row stride in halves

// Scratch (allocation-free requirement -> __device__ globals)
__device__ __align__(16) float g_isd[N_NODES_MAX];
__device__ __align__(16) __half g_h16[(size_t)N_NODES_MAX * D];  // GEMM out / gather src
__device__ __align__(16) __half g_z16[(size_t)N_NODES_MAX * D];  // gather out relu(agg+b)
__device__ int g_count[N_NODES_MAX];
__device__ __align__(16) int2 g_rowptr2[N_NODES_MAX];  // (start, end) per node
__device__ int g_cursor[N_NODES_MAX];
__device__ int g_total;                                 // atomic base for scan
__device__ __align__(16) int2 g_edges[E_MAX];          // (src, isd[src] bits)
__device__ int g_is64;
__device__ __align__(16) __half g_W1t[128 * 128];  // W1^T fp16 [n][k]
__device__ __align__(16) __half g_W2t[128 * 128];  // W2^T fp16 [n][k]
__device__ __align__(16) __half g_Wlt[64 * 128];   // Wl^T fp16, n padded 40->64

// ---------------------------------------------------------------------------
// init: zero histogram + scan base, detect edge dtype
// (int64 vs int32: node ids < 2^31 so int64 has all-zero odd 32-bit words)
// ---------------------------------------------------------------------------
__global__ void init_kernel(const unsigned int* __restrict__ w, int* count, int n) {
    int i = blockIdx.x * blockDim.x + threadIdx.x;
    if (i < n) count[i] = 0;
    if (i == 0) g_total = 0;
    if (blockIdx.x == 0) {
        __shared__ int any_nz;
        if (threadIdx.x == 0) any_nz = 0;
        __syncthreads();
        for (int j = threadIdx.x; j < 1024; j += blockDim.x)
            if (w[2 * j + 1] != 0u) any_nz = 1;
        __syncthreads();
        if (threadIdx.x == 0) g_is64 = any_nz ? 0 : 1;
    }
}

__device__ __forceinline__ int edge_at(const unsigned int* __restrict__ w,
                                       size_t pos, int is64) {
    return (int)(is64 ? w[2 * pos] : w[pos]);
}

// ---------------------------------------------------------------------------
// Histogram: 4 edges per thread; uint4 vectorized on the int32 path.
// ---------------------------------------------------------------------------
__global__ void hist_kernel(const unsigned int* __restrict__ ei, int* count, int E) {
    int base = (blockIdx.x * blockDim.x + threadIdx.x) * 4;
    if (base >= E) return;
    int is64 = g_is64;
    if (!is64 && base + 4 <= E) {
        uint4 d = *(const uint4*)(ei + (size_t)E + base);
        atomicAdd(count + (int)d.x, 1);
        atomicAdd(count + (int)d.y, 1);
        atomicAdd(count + (int)d.z, 1);
        atomicAdd(count + (int)d.w, 1);
    } else {
        for (int j = 0; j < 4 && base + j < E; j++)
            atomicAdd(count + edge_at(ei, (size_t)E + base + j, is64), 1);
    }
}

// ---------------------------------------------------------------------------
// Weight prep (one launch): W1t/W2t [128][128], Wlt [64][128] (n>=40 zero)
// ---------------------------------------------------------------------------
__global__ void wt_prep_kernel(const float* __restrict__ W1,
                               const float* __restrict__ W2,
                               const float* __restrict__ Wl,
                               __half* __restrict__ W1t, __half* __restrict__ W2t,
                               __half* __restrict__ Wlt) {
    int idx = blockIdx.x * blockDim.x + threadIdx.x;  // 40960 total
    if (idx < 32768) {
        int which = idx >> 14;
        int r = idx & 16383;
        int n = r >> 7, k = r & 127;
        const float* W = which ? W2 : W1;
        __half* Wt = which ? W2t : W1t;
        Wt[r] = __float2half_rn(W[k * 128 + n]);
    } else if (idx < 40960) {
        int r = idx - 32768;          // 0..8191
        int n = r >> 7, k = r & 127;  // n 0..63
        float v = (n < 40) ? Wl[k * 40 + n] : 0.f;
        Wlt[r] = __float2half_rn(v);
    }
}

// ---------------------------------------------------------------------------
// Order-independent single-pass "scan": each block claims its base via one
// atomicAdd on g_total; rows get disjoint [start,end) spans covering [0,E).
// Also emits isd = rsqrt(deg+1).
// ---------------------------------------------------------------------------
__global__ void scan_kernel(const int* __restrict__ count, int2* rowptr2,
                            int* cursor, float* isd, int n) {
    __shared__ int sm[256];
    __shared__ int s_base;
    const int t = threadIdx.x;
    const int base = blockIdx.x * 1024 + t * 4;

    int v[4];
#pragma unroll
    for (int j = 0; j < 4; j++) {
        int i = base + j;
        v[j] = (i < n) ? count[i] : 0;
        if (i < n) isd[i] = rsqrtf((float)v[j] + 1.0f);  // +1 self loop
    }
    int s = v[0] + v[1] + v[2] + v[3];
    sm[t] = s;
    __syncthreads();
    for (int off = 1; off < 256; off <<= 1) {
        int x = (t >= off) ? sm[t - off] : 0;
        __syncthreads();
        sm[t] += x;
        __syncthreads();
    }
    int local_excl = sm[t] - s;
    if (t == 255) s_base = atomicAdd(&g_total, sm[255]);
    __syncthreads();

    int start = s_base + local_excl;
#pragma unroll
    for (int j = 0; j < 4; j++) {
        int i = base + j;
        if (i < n) {
            rowptr2[i] = make_int2(start, start + v[j]);
            cursor[i] = start;
        }
        start += v[j];
    }
}

// ---------------------------------------------------------------------------
// Scatter: edges[pos] = (src, isd[src]). The dst factor of the norm is
// applied in the gather (register-resident there).
// ---------------------------------------------------------------------------
__global__ void scatter_kernel(const unsigned int* __restrict__ ei,
                               const float* __restrict__ isd,
                               int* cursor, int2* edges, int E) {
    int base = (blockIdx.x * blockDim.x + threadIdx.x) * 4;
    if (base >= E) return;
    int is64 = g_is64;
    if (!is64 && base + 4 <= E) {
        uint4 s4 = *(const uint4*)(ei + base);
        uint4 d4 = *(const uint4*)(ei + (size_t)E + base);
        int ss[4] = {(int)s4.x, (int)s4.y, (int)s4.z, (int)s4.w};
        int dd[4] = {(int)d4.x, (int)d4.y, (int)d4.z, (int)d4.w};
#pragma unroll
        for (int j = 0; j < 4; j++) {
            int pos = atomicAdd(cursor + dd[j], 1);
            edges[pos] = make_int2(ss[j], __float_as_int(isd[ss[j]]));
        }
    } else {
        for (int j = 0; j < 4 && base + j < E; j++) {
            int s = edge_at(ei, (size_t)(base + j), is64);
            int d = edge_at(ei, (size_t)E + base + j, is64);
            int pos = atomicAdd(cursor + d, 1);
            edges[pos] = make_int2(s, __float_as_int(isd[s]));
        }
    }
}

// ---------------------------------------------------------------------------
// Tensor-core GEMM: h16[M,128] = A[M,128] @ W (fp16 in, fp32 accum, fp16 out)
// IN_HALF=false: A fp32 (layer-1 x). IN_HALF=true: A fp16 (z16, pre-activated).
// ---------------------------------------------------------------------------
__device__ __forceinline__ void mma16816(float c[4], unsigned a0, unsigned a1,
                                         unsigned a2, unsigned a3,
                                         unsigned b0, unsigned b1) {
    asm volatile(
        "mma.sync.aligned.m16n8k16.row.col.f32.f16.f16.f32 "
        "{%0,%1,%2,%3}, {%4,%5,%6,%7}, {%8,%9}, {%0,%1,%2,%3};"
        : "+f"(c[0]), "+f"(c[1]), "+f"(c[2]), "+f"(c[3])
        : "r"(a0), "r"(a1), "r"(a2), "r"(a3), "r"(b0), "r"(b1));
}

template <bool IN_HALF>
__global__ void gemm_tc_kernel(const void* __restrict__ Ain,
                               const __half* __restrict__ Wt16,  // [n][k]
                               __half* __restrict__ Hout,
                               int M) {
    extern __shared__ __half smh[];
    __half* As = smh;              // 64 x SPAD
    __half* Bs = smh + 64 * SPAD;  // 128 x SPAD

    const int tid = threadIdx.x;
    const int r0 = blockIdx.x * 64;

    {
        const uint4* src = (const uint4*)Wt16;
#pragma unroll
        for (int i = 0; i < 8; i++) {
            int idx = tid + i * 256;          // 2048 uint4
            int row = idx >> 4, c8 = idx & 15;
            *(uint4*)(Bs + row * SPAD + c8 * 8) = src[idx];
        }
    }
    if (IN_HALF) {
        const uint4* src = (const uint4*)Ain;
#pragma unroll
        for (int i = 0; i < 4; i++) {
            int idx = tid + i * 256;           // 1024 uint4
            int lr = idx >> 4, c8 = idx & 15;
            int row = r0 + lr;
            uint4 v = make_uint4(0u, 0u, 0u, 0u);
            if (row < M) v = src[(size_t)row * 16 + c8];
            *(uint4*)(As + lr * SPAD + c8 * 8) = v;
        }
    } else {
        const float4* src = (const float4*)Ain;
#pragma unroll
        for (int i = 0; i < 8; i++) {
            int idx = tid + i * 256;           // 2048 float4
            int lr = idx >> 5, c4 = idx & 31;
            int row = r0 + lr;
            float4 v = make_float4(0.f, 0.f, 0.f, 0.f);
            if (row < M) v = src[(size_t)row * 32 + c4];
            __half2 lo = __floats2half2_rn(v.x, v.y);
            __half2 hi = __floats2half2_rn(v.z, v.w);
            uint2 pack;
            pack.x = *(unsigned*)&lo;
            pack.y = *(unsigned*)&hi;
            *(uint2*)(As + lr * SPAD + c4 * 4) = pack;
        }
    }
    __syncthreads();

    const int warp = tid >> 5;
    const int lane = tid & 31;
    const int g = lane >> 2;
    const int tig = lane & 3;
    const int m0 = (warp & 3) * 16;
    const int n0 = (warp >> 2) * 64;

    float c[8][4] = {};
    const __half* Aw = As + (m0 + g) * SPAD + tig * 2;
    const __half* Bw = Bs + (n0 + g) * SPAD + tig * 2;

#pragma unroll
    for (int ks = 0; ks < 8; ks++) {
        int k0 = ks * 16;
        unsigned a0 = *(const unsigned*)(Aw + k0);
        unsigned a1 = *(const unsigned*)(Aw + k0 + 8 * SPAD);
        unsigned a2 = *(const unsigned*)(Aw + k0 + 8);
        unsigned a3 = *(const unsigned*)(Aw + k0 + 8 * SPAD + 8);
#pragma unroll
        for (int t = 0; t < 8; t++) {
            unsigned b0 = *(const unsigned*)(Bw + t * 8 * SPAD + k0);
            unsigned b1 = *(const unsigned*)(Bw + t * 8 * SPAD + k0 + 8);
            mma16816(c[t], a0, a1, a2, a3, b0, b1);
        }
    }

#pragma unroll
    for (int t = 0; t < 8; t++) {
        int col = n0 + t * 8 + tig * 2;
        int row0 = r0 + m0 + g;
        int row1 = row0 + 8;
        if (row0 < M) {
            __half2 p = __floats2half2_rn(c[t][0], c[t][1]);
            *(unsigned*)(Hout + (size_t)row0 * 128 + col) = *(unsigned*)&p;
        }
        if (row1 < M) {
            __half2 p = __floats2half2_rn(c[t][2], c[t][3]);
            *(unsigned*)(Hout + (size_t)row1 * 128 + col) = *(unsigned*)&p;
        }
    }
}

// ---------------------------------------------------------------------------
// CSR gather + fused epilogue: z16[n] = (half)relu(agg[n] + bias)
// agg[n] = h[n]/deg(n) + sum_e h[src_e] * (isd_src_e * isd[n])
// One warp per node; lane owns 4 columns. 8 edges in flight per iteration
// (doubled MLP vs round 13 to close the latency gap to the LTS byte floor).
// ---------------------------------------------------------------------------
__device__ __forceinline__ void fma4_h(float4& acc, uint2 p, float w) {
    float2 lo = __half22float2(*(__half2*)&p.x);
    float2 hi = __half22float2(*(__half2*)&p.y);
    acc.x += lo.x * w; acc.y += lo.y * w;
    acc.z += hi.x * w; acc.w += hi.y * w;
}

__global__ void gather_kernel(const int2* __restrict__ edges,
                              const int2* __restrict__ rowptr2,
                              const __half* __restrict__ h,
                              const float* __restrict__ isd,
                              const float* __restrict__ bias,
                              __half* __restrict__ z, int N) {
    int node = (blockIdx.x * blockDim.x + threadIdx.x) >> 5;
    int lane = threadIdx.x & 31;
    if (node >= N) return;

    const uint2* h4 = (const uint2*)h;
    int2 span = rowptr2[node];
    int start = span.x;
    int end = span.y;

    float isd_d = isd[node];
    float4 acc = make_float4(0.f, 0.f, 0.f, 0.f);
    fma4_h(acc, h4[(size_t)node * 32 + lane], isd_d * isd_d);  // self loop 1/deg

    int e = start;
    for (; e + 8 <= end; e += 8) {
        int2 e0 = edges[e + 0];
        int2 e1 = edges[e + 1];
        int2 e2 = edges[e + 2];
        int2 e3 = edges[e + 3];
        int2 e4 = edges[e + 4];
        int2 e5 = edges[e + 5];
        int2 e6 = edges[e + 6];
        int2 e7 = edges[e + 7];
        uint2 v0 = h4[(size_t)e0.x * 32 + lane];
        uint2 v1 = h4[(size_t)e1.x * 32 + lane];
        uint2 v2 = h4[(size_t)e2.x * 32 + lane];
        uint2 v3 = h4[(size_t)e3.x * 32 + lane];
        uint2 v4 = h4[(size_t)e4.x * 32 + lane];
        uint2 v5 = h4[(size_t)e5.x * 32 + lane];
        uint2 v6 = h4[(size_t)e6.x * 32 + lane];
        uint2 v7 = h4[(size_t)e7.x * 32 + lane];
        fma4_h(acc, v0, __int_as_float(e0.y) * isd_d);
        fma4_h(acc, v1, __int_as_float(e1.y) * isd_d);
        fma4_h(acc, v2, __int_as_float(e2.y) * isd_d);
        fma4_h(acc, v3, __int_as_float(e3.y) * isd_d);
        fma4_h(acc, v4, __int_as_float(e4.y) * isd_d);
        fma4_h(acc, v5, __int_as_float(e5.y) * isd_d);
        fma4_h(acc, v6, __int_as_float(e6.y) * isd_d);
        fma4_h(acc, v7, __int_as_float(e7.y) * isd_d);
    }
    for (; e < end; e++) {
        int2 ed = edges[e];
        fma4_h(acc, h4[(size_t)ed.x * 32 + lane], __int_as_float(ed.y) * isd_d);
    }

    float4 b = ((const float4*)bias)[lane];
    acc.x = fmaxf(acc.x + b.x, 0.f);
    acc.y = fmaxf(acc.y + b.y, 0.f);
    acc.z = fmaxf(acc.z + b.z, 0.f);
    acc.w = fmaxf(acc.w + b.w, 0.f);
    __half2 lo = __floats2half2_rn(acc.x, acc.y);
    __half2 hi = __floats2half2_rn(acc.z, acc.w);
    uint2 p;
    p.x = *(unsigned*)&lo;
    p.y = *(unsigned*)&hi;
    ((uint2*)z)[(size_t)node * 32 + lane] = p;
}

// ---------------------------------------------------------------------------
// Tensor-core head: out[M,40] = z16[M,128] @ Wl + bl (Wlt [64][128] fp16)
// ---------------------------------------------------------------------------
__global__ void head_tc_kernel(const __half* __restrict__ z,
                               const __half* __restrict__ Wlt,  // [64][128]
                               const float* __restrict__ bl,
                               float* __restrict__ out,
                               int M) {
    extern __shared__ __half smh[];
    __half* As = smh;              // 64 x SPAD
    __half* Bs = smh + 64 * SPAD;  // 64 x SPAD

    const int tid = threadIdx.x;   // 256
    const int r0 = blockIdx.x * 64;

    {
        const uint4* src = (const uint4*)Wlt;   // 1024 uint4
#pragma unroll
        for (int i = 0; i < 4; i++) {
            int idx = tid + i * 256;
            int row = idx >> 4, c8 = idx & 15;
            *(uint4*)(Bs + row * SPAD + c8 * 8) = src[idx];
        }
    }
    {
        const uint4* src = (const uint4*)z;
#pragma unroll
        for (int i = 0; i < 4; i++) {
            int idx = tid + i * 256;           // 1024 uint4
            int lr = idx >> 4, c8 = idx & 15;
            int row = r0 + lr;
            uint4 v = make_uint4(0u, 0u, 0u, 0u);
            if (row < M) v = src[(size_t)row * 16 + c8];
            *(uint4*)(As + lr * SPAD + c8 * 8) = v;
        }
    }
    __syncthreads();

    const int warp = tid >> 5;
    const int lane = tid & 31;
    const int g = lane >> 2;
    const int tig = lane & 3;
    const int m0 = (warp & 3) * 16;
    const int n0 = (warp >> 2) * 32;

    float c[4][4] = {};
    const __half* Aw = As + (m0 + g) * SPAD + tig * 2;
    const __half* Bw = Bs + (n0 + g) * SPAD + tig * 2;

#pragma unroll
    for (int ks = 0; ks < 8; ks++) {
        int k0 = ks * 16;
        unsigned a0 = *(const unsigned*)(Aw + k0);
        unsigned a1 = *(const unsigned*)(Aw + k0 + 8 * SPAD);
        unsigned a2 = *(const unsigned*)(Aw + k0 + 8);
        unsigned a3 = *(const unsigned*)(Aw + k0 + 8 * SPAD + 8);
#pragma unroll
        for (int t = 0; t < 4; t++) {
            unsigned b0 = *(const unsigned*)(Bw + t * 8 * SPAD + k0);
            unsigned b1 = *(const unsigned*)(Bw + t * 8 * SPAD + k0 + 8);
            mma16816(c[t], a0, a1, a2, a3, b0, b1);
        }
    }

#pragma unroll
    for (int t = 0; t < 4; t++) {
        int col = n0 + t * 8 + tig * 2;
        if (col < 40) {
            float b0 = bl[col], b1 = bl[col + 1];
            int row0 = r0 + m0 + g;
            int row1 = row0 + 8;
            if (row0 < M) {
                float2 p = make_float2(c[t][0] + b0, c[t][1] + b1);
                *(float2*)(out + (size_t)row0 * 40 + col) = p;
            }
            if (row1 < M) {
                float2 p = make_float2(c[t][2] + b0, c[t][3] + b1);
                *(float2*)(out + (size_t)row1 * 40 + col) = p;
            }
        }
    }
}

// ---------------------------------------------------------------------------
extern "C" void kernel_launch(void* const* d_in, const int* in_sizes, int n_in,
                              void* d_out, int out_size) {
    const float* x = (const float*)d_in[0];
    const unsigned int* ei = (const unsigned int*)d_in[1];
    const float* W1 = (const float*)d_in[2];
    const float* b1 = (const float*)d_in[3];
    const float* W2 = (const float*)d_in[4];
    const float* b2 = (const float*)d_in[5];
    const float* Wl = (const float*)d_in[6];
    const float* bl = (const float*)d_in[7];
    float* out = (float*)d_out;

    const int N = in_sizes[0] / D;     // 100000
    const int E = in_sizes[1] / 2;     // 3200000

    float* isd;
    __half *h16, *z16, *W1t, *W2t, *Wlt;
    int *count, *cursor;
    int2 *rowptr2, *edges;
    cudaGetSymbolAddress((void**)&isd, g_isd);
    cudaGetSymbolAddress((void**)&h16, g_h16);
    cudaGetSymbolAddress((void**)&z16, g_z16);
    cudaGetSymbolAddress((void**)&count, g_count);
    cudaGetSymbolAddress((void**)&rowptr2, g_rowptr2);
    cudaGetSymbolAddress((void**)&cursor, g_cursor);
    cudaGetSymbolAddress((void**)&edges, g_edges);
    cudaGetSymbolAddress((void**)&W1t, g_W1t);
    cudaGetSymbolAddress((void**)&W2t, g_W2t);
    cudaGetSymbolAddress((void**)&Wlt, g_Wlt);

    const int gemm_smem = (64 * SPAD + 128 * SPAD) * sizeof(__half);  // ~52 KB
    const int head_smem = (64 * SPAD + 64 * SPAD) * sizeof(__half);   // ~35 KB
    cudaFuncSetAttribute(gemm_tc_kernel<false>,
                         cudaFuncAttributeMaxDynamicSharedMemorySize, gemm_smem);
    cudaFuncSetAttribute(gemm_tc_kernel<true>,
                         cudaFuncAttributeMaxDynamicSharedMemorySize, gemm_smem);
    cudaFuncSetAttribute(head_tc_kernel,
                         cudaFuncAttributeMaxDynamicSharedMemorySize, head_smem);

    // Lazy one-time host-side resources (validated pattern from round 11).
    static cudaStream_t s2 = nullptr;
    static cudaEvent_t ev_fork = nullptr, ev_join = nullptr;
    if (s2 == nullptr) {
        cudaStreamCreateWithFlags(&s2, cudaStreamNonBlocking);
        cudaEventCreateWithFlags(&ev_fork, cudaEventDisableTiming);
        cudaEventCreateWithFlags(&ev_join, cudaEventDisableTiming);
    }

    const int nb = (N + 255) / 256;
    const int e4 = (E + 3) / 4;
    const int eb4 = (e4 + 255) / 256;
    const int scan_grid = (N + 1023) / 1024;
    const int gemm_grid = (N + 63) / 64;
    const int gather_grid = (N + 7) / 8;
    const int head_grid = (N + 63) / 64;

    // Fork immediately: side stream does wt_prep -> gemm1 (x @ W1 -> h16);
    // neither depends on init. Main stream does init -> hist -> scan ->
    // scatter (dtype flag g_is64 is produced by init before hist on the
    // same stream). Different resources: gemm tensor/smem-bound vs CSR
    // chain L2-atomic-bound (round-11-validated overlap).
    cudaEventRecord(ev_fork, 0);
    cudaStreamWaitEvent(s2, ev_fork, 0);
    wt_prep_kernel<<<160, 256, 0, s2>>>(W1, W2, Wl, W1t, W2t, Wlt);
    gemm_tc_kernel<false><<<gemm_grid, 256, gemm_smem, s2>>>(x, W1t, h16, N);
    cudaEventRecord(ev_join, s2);

    // CSR build on main stream
    init_kernel<<<nb, 256>>>(ei, count, N);
    hist_kernel<<<eb4, 256>>>(ei, count, E);
    scan_kernel<<<scan_grid, 256>>>(count, rowptr2, cursor, isd, N);
    scatter_kernel<<<eb4, 256>>>(ei, isd, cursor, edges, E);

    cudaStreamWaitEvent(0, ev_join, 0);  // gather1 needs h16 + CSR (+ weights
                                         // for later kernels, same s2 order)

    // 1. layer 1 aggregate: z16 = relu(agg(h16) + b1)
    gather_kernel<<<gather_grid, 256>>>(edges, rowptr2, h16, isd, b1, z16, N);

    // 2. layer 2: h16 = (half)(z16 @ W2); z16 = relu(agg + b2)
    gemm_tc_kernel<true><<<gemm_grid, 256, gemm_smem>>>(z16, W2t, h16, N);
    gather_kernel<<<gather_grid, 256>>>(edges, rowptr2, h16, isd, b2, z16, N);

    // 3. head: out = z16 @ Wl + bl   (tensor cores)
    head_tc_kernel<<<head_grid, 256, head_smem>>>(z16, Wlt, bl, out, N);
}